// round 1
// baseline (speedup 1.0000x reference)
#include <cuda_runtime.h>

#define NN   8192      // nodes per graph
#define NE   131072    // edges per graph
#define NB   256       // batches
#define NHF  128       // GCN hidden
#define FIN  64        // input features
#define H3   384       // 3*NHF (concat of 3 GCN layers)
#define D6   768       // set2set channel dim
#define D12  1536
#define G4   3072      // 4*D6 (LSTM gates)

// ---------------- scratch (static device memory; no allocation) ----------------
__device__ __align__(16) float g_h[2][NN * H3];     // [ns-pre] concat GCN outputs
__device__ __align__(16) float g_x[2][NN * D6];     // f = [ns, r]
__device__ __align__(16) float g_xw[NN * NHF];      // X@W temp
__device__ float g_deg[NN];
__device__ float g_dinv[2][NN];
__device__ int   g_starts[2][NB + 1];
__device__ float g_hv[D6];                          // step-1 LSTM h (shared all batches/graphs)
__device__ float g_cv[D6];                          // step-1 LSTM c
__device__ float g_cvec[G4];                        // step-2 constant gate part
__device__ float g_e[NN];                           // attention scores
__device__ __align__(16) float g_rb[NB * D6];       // step-1 readout r
__device__ __align__(16) float g_gates[NB * G4];
__device__ __align__(16) float g_hb[NB * D6];       // step-2 h per batch
__device__ __align__(16) float g_z[NB * G4];        // [h2_g1, r2_g1, h2_g2, r2_g2]
__device__ __align__(16) float g_z1[NB * 256];
__device__ __align__(16) float g_z2[NB * 128];

__device__ __forceinline__ float wredsum(float v) {
#pragma unroll
    for (int o = 16; o; o >>= 1) v += __shfl_xor_sync(0xffffffffu, v, o);
    return v;
}
__device__ __forceinline__ float sgm(float x) { return 1.f / (1.f + expf(-x)); }

// ---------------- degree / normalization ----------------
__global__ void k_zero_deg() {
    int i = blockIdx.x * blockDim.x + threadIdx.x;
    if (i < NN) g_deg[i] = 0.f;
}
__global__ void k_deg(const int* __restrict__ ei, const float* __restrict__ ew) {
    int e = blockIdx.x * blockDim.x + threadIdx.x;
    if (e < NE) atomicAdd(&g_deg[ei[NE + e]], ew[e]);
}
__global__ void k_dinv(int gidx) {
    int i = blockIdx.x * blockDim.x + threadIdx.x;
    if (i < NN) g_dinv[gidx][i] = rsqrtf(g_deg[i] + 1.0f);  // +1: self loop weight
}

// ---------------- X @ W  (warp per node row; W rows L1-resident) ----------------
__global__ void k_xw(const float* __restrict__ Xext, int useExt, int gidx, int srcoff,
                     int K, const float* __restrict__ W) {
    int warp = blockIdx.x * 8 + (threadIdx.x >> 5);
    int lane = threadIdx.x & 31;
    if (warp >= NN) return;
    const float* xr;
    int ldx;
    if (useExt) { xr = Xext + (size_t)warp * FIN; ldx = FIN; (void)ldx; }
    else        { xr = g_h[gidx] + (size_t)warp * H3 + srcoff; }
    float a0 = 0.f, a1 = 0.f, a2 = 0.f, a3 = 0.f;
    for (int k = 0; k < K; k++) {
        float xv = xr[k];
        const float* wr = W + k * NHF;
        a0 += xv * wr[lane];
        a1 += xv * wr[lane + 32];
        a2 += xv * wr[lane + 64];
        a3 += xv * wr[lane + 96];
    }
    float* o = g_xw + (size_t)warp * NHF;
    o[lane] = a0; o[lane + 32] = a1; o[lane + 64] = a2; o[lane + 96] = a3;
}

// init aggregation with bias + self-loop term
__global__ void k_gcn_init(int gidx, int off, const float* __restrict__ bias) {
    int i = blockIdx.x * blockDim.x + threadIdx.x;
    if (i >= NN * NHF) return;
    int n = i >> 7, f = i & 127;
    float di = g_dinv[gidx][n];
    g_h[gidx][(size_t)n * H3 + off + f] = bias[f] + di * di * g_xw[i];
}

// edge scatter: h[d] += dinv[s]*w*dinv[d] * xw[s]
__global__ void k_gcn_scatter(const int* __restrict__ ei, const float* __restrict__ ew,
                              int gidx, int off) {
    long long i = (long long)blockIdx.x * blockDim.x + threadIdx.x;
    if (i >= (long long)NE * NHF) return;
    int e = (int)(i >> 7), f = (int)(i & 127);
    int s = ei[e], d = ei[NE + e];
    float nm = g_dinv[gidx][s] * ew[e] * g_dinv[gidx][d];
    atomicAdd(&g_h[gidx][(size_t)d * H3 + off + f], nm * g_xw[(size_t)s * NHF + f]);
}

__global__ void k_leaky(int gidx, int off) {
    int i = blockIdx.x * blockDim.x + threadIdx.x;
    if (i >= NN * NHF) return;
    int n = i >> 7, f = i & 127;
    float* p = &g_h[gidx][(size_t)n * H3 + off + f];
    float v = *p;
    *p = (v >= 0.f) ? v : 0.2f * v;
}

// ---------------- L2 normalize rows into x[:, :384] ----------------
__global__ void k_l2(int gidx) {
    int warp = blockIdx.x * 8 + (threadIdx.x >> 5);
    int lane = threadIdx.x & 31;
    if (warp >= NN) return;
    const float* hr = g_h[gidx] + (size_t)warp * H3;
    float ss = 0.f;
#pragma unroll
    for (int t = 0; t < 12; t++) { float v = hr[lane + 32 * t]; ss += v * v; }
    ss = wredsum(ss);
    float inv = 1.f / fmaxf(sqrtf(ss), 1e-12f);
    float* xr = g_x[gidx] + (size_t)warp * D6;
#pragma unroll
    for (int t = 0; t < 12; t++) xr[lane + 32 * t] = hr[lane + 32 * t] * inv;
}

// ---------------- CSR starts from sorted batch ids ----------------
__global__ void k_starts(const int* __restrict__ batch, int gidx) {
    int n = blockIdx.x * blockDim.x + threadIdx.x;
    if (n >= NN) return;
    int b = batch[n];
    if (n == 0) {
        for (int bb = 0; bb <= b; bb++) g_starts[gidx][bb] = 0;
    } else {
        int pb = batch[n - 1];
        if (pb != b) for (int bb = pb + 1; bb <= b; bb++) g_starts[gidx][bb] = n;
    }
    if (n == NN - 1) {
        for (int bb = b + 1; bb <= NB; bb++) g_starts[gidx][bb] = NN;
    }
}

// ---------------- block-diagonal interaction: r1_i = Σ_j (ns_i·nv_j) nv_j ----------------
__global__ void k_interact() {
    int b = blockIdx.x;
    int s1 = g_starts[0][b], e1 = g_starts[0][b + 1];
    int s2 = g_starts[1][b], e2 = g_starts[1][b + 1];
    int n1 = e1 - s1, n2 = e2 - s2, tot = n1 + n2;
    int lane = threadIdx.x & 31, w = threadIdx.x >> 5;
    for (int t = w; t < tot; t += 8) {
        const float* src;
        const float* oth;
        float* out;
        int row, obase, ocnt;
        if (t < n1) { row = s1 + t;        src = g_x[0]; oth = g_x[1]; obase = s2; ocnt = n2; out = g_x[0]; }
        else        { row = s2 + (t - n1); src = g_x[1]; oth = g_x[0]; obase = s1; ocnt = n1; out = g_x[1]; }
        const float* sr = src + (size_t)row * D6;
        float sv[12], acc[12];
#pragma unroll
        for (int q = 0; q < 12; q++) { sv[q] = sr[lane + 32 * q]; acc[q] = 0.f; }
        for (int jj = 0; jj < ocnt; jj++) {
            const float* vr = oth + (size_t)(obase + jj) * D6;
            float vv[12], p = 0.f;
#pragma unroll
            for (int q = 0; q < 12; q++) { vv[q] = vr[lane + 32 * q]; p += sv[q] * vv[q]; }
            p = wredsum(p);
#pragma unroll
            for (int q = 0; q < 12; q++) acc[q] += p * vv[q];
        }
        float* orow = out + (size_t)row * D6 + H3;
#pragma unroll
        for (int q = 0; q < 12; q++) orow[lane + 32 * q] = acc[q];
    }
}

// ---------------- Set2Set ----------------
// step-1 LSTM: gates = bih+bhh (identical for all batches/graphs)
__global__ void k_lstm1(const float* __restrict__ bih, const float* __restrict__ bhh) {
    int j = blockIdx.x * blockDim.x + threadIdx.x;
    if (j >= D6) return;
    float gi = bih[j] + bhh[j];
    float gg = bih[2 * D6 + j] + bhh[2 * D6 + j];
    float go = bih[3 * D6 + j] + bhh[3 * D6 + j];
    float c = sgm(gi) * tanhf(gg);     // σ(gf)*c0 = 0
    g_cv[j] = c;
    g_hv[j] = sgm(go) * tanhf(c);
}

// e[n] = x[n, :768] · h_row
__global__ void k_escore(int gidx, int useHb, const int* __restrict__ batch) {
    int warp = blockIdx.x * 8 + (threadIdx.x >> 5);
    int lane = threadIdx.x & 31;
    if (warp >= NN) return;
    const float* xr = g_x[gidx] + (size_t)warp * D6;
    const float* hr = useHb ? (g_hb + (size_t)batch[warp] * D6) : g_hv;
    float p = 0.f;
#pragma unroll
    for (int t = 0; t < 24; t++) p += xr[lane + 32 * t] * hr[lane + 32 * t];
    p = wredsum(p);
    if (lane == 0) g_e[warp] = p;
}

// segment softmax + weighted readout r[b]
__global__ void k_attn(int gidx, int mode) {   // mode 0: -> g_rb ; mode 1: -> g_z r-slot
    int b = blockIdx.x;
    int s = g_starts[gidx][b], e = g_starts[gidx][b + 1];
    int tid = threadIdx.x;
    float* rout;
    size_t rstride;
    if (mode == 0) { rout = g_rb + (size_t)b * D6; rstride = 1; }
    else           { rout = g_z + (size_t)b * G4 + (gidx ? D12 : 0) + D6; rstride = 1; }
    (void)rstride;
    if (e <= s) {
        for (int f = tid; f < D6; f += 256) rout[f] = 0.f;
        return;
    }
    __shared__ float red[256];
    __shared__ float ee[256];
    const float* x = g_x[gidx];
    float lm = -3.4e38f;
    for (int n = s + tid; n < e; n += 256) lm = fmaxf(lm, g_e[n]);
    red[tid] = lm; __syncthreads();
    for (int o = 128; o > 0; o >>= 1) { if (tid < o) red[tid] = fmaxf(red[tid], red[tid + o]); __syncthreads(); }
    float m = red[0]; __syncthreads();
    float ls = 0.f;
    for (int n = s + tid; n < e; n += 256) ls += expf(g_e[n] - m);
    red[tid] = ls; __syncthreads();
    for (int o = 128; o > 0; o >>= 1) { if (tid < o) red[tid] += red[tid + o]; __syncthreads(); }
    float S = red[0]; __syncthreads();
    float a0 = 0.f, a1 = 0.f, a2 = 0.f;
    for (int base = s; base < e; base += 256) {
        int cnt = min(256, e - base);
        if (tid < cnt) ee[tid] = expf(g_e[base + tid] - m);
        __syncthreads();
        for (int t = 0; t < cnt; t++) {
            float w = ee[t];
            const float* xr = x + (size_t)(base + t) * D6;
            a0 += w * xr[tid];
            a1 += w * xr[tid + 256];
            a2 += w * xr[tid + 512];
        }
        __syncthreads();
    }
    float inv = 1.f / S;
    rout[tid] = a0 * inv;
    rout[tid + 256] = a1 * inv;
    rout[tid + 512] = a2 * inv;
}

// constvec[g] = bih+bhh + Σ_k hv[k]*(Wih[g,k] + Whh[g,k])   (warp per g)
__global__ void k_cvec(const float* __restrict__ Wih, const float* __restrict__ Whh,
                       const float* __restrict__ bih, const float* __restrict__ bhh) {
    int g = blockIdx.x * 8 + (threadIdx.x >> 5);
    int lane = threadIdx.x & 31;
    if (g >= G4) return;
    const float* wi = Wih + (size_t)g * D12;
    const float* wh = Whh + (size_t)g * D6;
    float p = 0.f;
#pragma unroll
    for (int t = 0; t < 24; t++) {
        int k = lane + 32 * t;
        p += g_hv[k] * (wi[k] + wh[k]);
    }
    p = wredsum(p);
    if (lane == 0) g_cvec[g] = bih[g] + bhh[g] + p;
}

// gates2 = g_rb @ WihR^T + cvec   (tiled 64x64, 4x4 micro)
__global__ void k_gates2(const float* __restrict__ Wih) {
    __shared__ float As[16][64];
    __shared__ float Bs[16][68];
    int tid = threadIdx.x, tx = tid & 15, ty = tid >> 4;
    int colBase = blockIdx.x * 64, rowBase = blockIdx.y * 64;
    const float* B = Wih + D6;   // right half of Wih rows
    float acc[4][4] = {};
    for (int k0 = 0; k0 < D6; k0 += 16) {
#pragma unroll
        for (int l = 0; l < 4; l++) {
            int idx = tid + l * 256;
            int m = idx >> 4, kk = idx & 15;
            As[kk][m] = g_rb[(size_t)(rowBase + m) * D6 + k0 + kk];
            Bs[kk][m] = B[(size_t)(colBase + m) * D12 + k0 + kk];
        }
        __syncthreads();
#pragma unroll
        for (int kk = 0; kk < 16; kk++) {
            float av[4], bv[4];
#pragma unroll
            for (int i = 0; i < 4; i++) av[i] = As[kk][ty * 4 + i];
#pragma unroll
            for (int j = 0; j < 4; j++) bv[j] = Bs[kk][tx * 4 + j];
#pragma unroll
            for (int i = 0; i < 4; i++)
#pragma unroll
                for (int j = 0; j < 4; j++) acc[i][j] += av[i] * bv[j];
        }
        __syncthreads();
    }
#pragma unroll
    for (int i = 0; i < 4; i++) {
        int row = rowBase + ty * 4 + i;
#pragma unroll
        for (int j = 0; j < 4; j++) {
            int col = colBase + tx * 4 + j;
            g_gates[(size_t)row * G4 + col] = acc[i][j] + g_cvec[col];
        }
    }
}

// step-2 LSTM: per (b,j); also writes h2 into z
__global__ void k_lstm2(int gidx) {
    int i = blockIdx.x * blockDim.x + threadIdx.x;
    if (i >= NB * D6) return;
    int b = i / D6, j = i - b * D6;
    const float* g = g_gates + (size_t)b * G4;
    float gi = g[j], gf = g[D6 + j], gg = g[2 * D6 + j], go = g[3 * D6 + j];
    float c = sgm(gf) * g_cv[j] + sgm(gi) * tanhf(gg);
    float h = sgm(go) * tanhf(c);
    g_hb[i] = h;
    g_z[(size_t)b * G4 + (gidx ? D12 : 0) + j] = h;
}

// ---------------- MLP (warp-dot, float4) ----------------
__global__ void k_mlp1(const float* __restrict__ Wp1, const float* __restrict__ bp1) {
    int gw = (blockIdx.x * blockDim.x + threadIdx.x) >> 5;
    int lane = threadIdx.x & 31;
    if (gw >= NB * 256) return;
    int b = gw >> 8, o = gw & 255;
    const float4* a = (const float4*)(g_z + (size_t)b * G4);
    const float4* w = (const float4*)(Wp1 + (size_t)o * G4);
    float p = 0.f;
#pragma unroll
    for (int t = lane; t < G4 / 4; t += 32) {
        float4 x = a[t], y = w[t];
        p += x.x * y.x + x.y * y.y + x.z * y.z + x.w * y.w;
    }
    p = wredsum(p);
    if (lane == 0) g_z1[(size_t)b * 256 + o] = fmaxf(p + bp1[o], 0.f);
}
__global__ void k_mlp2(const float* __restrict__ Wp2, const float* __restrict__ bp2) {
    int gw = (blockIdx.x * blockDim.x + threadIdx.x) >> 5;
    int lane = threadIdx.x & 31;
    if (gw >= NB * 128) return;
    int b = gw >> 7, o = gw & 127;
    const float4* a = (const float4*)(g_z1 + (size_t)b * 256);
    const float4* w = (const float4*)(Wp2 + (size_t)o * 256);
    float p = 0.f;
#pragma unroll
    for (int t = lane; t < 64; t += 32) {
        float4 x = a[t], y = w[t];
        p += x.x * y.x + x.y * y.y + x.z * y.z + x.w * y.w;
    }
    p = wredsum(p);
    if (lane == 0) g_z2[(size_t)b * 128 + o] = fmaxf(p + bp2[o], 0.f);
}
__global__ void k_final(const float* __restrict__ Wp3, const float* __restrict__ bp3,
                        float* __restrict__ out) {
    int b = blockIdx.x * blockDim.x + threadIdx.x;
    if (b >= NB) return;
    float p = bp3[0];
#pragma unroll 16
    for (int k = 0; k < 128; k++) p += g_z2[(size_t)b * 128 + k] * Wp3[k];
    out[b] = 1.f / (1.f + expf(-p));
}

// ---------------- launch sequence ----------------
extern "C" void kernel_launch(void* const* d_in, const int* in_sizes, int n_in,
                              void* d_out, int out_size) {
    const float* feat[2] = { (const float*)d_in[0], (const float*)d_in[1] };
    const float* ea[2]   = { (const float*)d_in[2], (const float*)d_in[3] };
    const float* W[3]    = { (const float*)d_in[4], (const float*)d_in[6], (const float*)d_in[8] };
    const float* bW[3]   = { (const float*)d_in[5], (const float*)d_in[7], (const float*)d_in[9] };
    const float* Wih = (const float*)d_in[10];
    const float* bih = (const float*)d_in[11];
    const float* Whh = (const float*)d_in[12];
    const float* bhh = (const float*)d_in[13];
    const float* Wp1 = (const float*)d_in[14];
    const float* bp1 = (const float*)d_in[15];
    const float* Wp2 = (const float*)d_in[16];
    const float* bp2 = (const float*)d_in[17];
    const float* Wp3 = (const float*)d_in[18];
    const float* bp3 = (const float*)d_in[19];
    const int* ei[2]    = { (const int*)d_in[20], (const int*)d_in[21] };
    const int* batch[2] = { (const int*)d_in[22], (const int*)d_in[23] };
    float* out = (float*)d_out;

    const int T = 256;
    const int nodeBlk = (NN + T - 1) / T;                 // 32
    const int warpNodeBlk = NN / 8;                       // 1024 (warp per node)
    const int featBlk = (NN * NHF) / T;                   // 4096
    const int edgeFeatBlk = (int)(((long long)NE * NHF) / T);  // 65536

    // GCN stacks
    for (int g = 0; g < 2; g++) {
        k_zero_deg<<<nodeBlk, T>>>();
        k_deg<<<(NE + T - 1) / T, T>>>(ei[g], ea[g]);
        k_dinv<<<nodeBlk, T>>>(g);
        for (int l = 0; l < 3; l++) {
            int srcoff = (l == 2) ? NHF : 0;   // layer2 reads layer1 output at col 128
            int K = (l == 0) ? FIN : NHF;
            k_xw<<<warpNodeBlk, T>>>((l == 0) ? feat[g] : nullptr, (l == 0) ? 1 : 0,
                                     g, srcoff, K, W[l]);
            k_gcn_init<<<featBlk, T>>>(g, l * NHF, bW[l]);
            k_gcn_scatter<<<edgeFeatBlk, T>>>(ei[g], ea[g], g, l * NHF);
            k_leaky<<<featBlk, T>>>(g, l * NHF);
        }
        k_l2<<<warpNodeBlk, T>>>(g);
    }

    // CSR segment starts + block-diagonal interaction
    k_starts<<<nodeBlk, T>>>(batch[0], 0);
    k_starts<<<nodeBlk, T>>>(batch[1], 1);
    k_interact<<<NB, T>>>();

    // Set2Set shared precompute
    k_lstm1<<<(D6 + T - 1) / T, T>>>(bih, bhh);
    k_cvec<<<G4 / 8, T>>>(Wih, Whh, bih, bhh);

    for (int g = 0; g < 2; g++) {
        // step 1 attention -> r
        k_escore<<<warpNodeBlk, T>>>(g, 0, batch[g]);
        k_attn<<<NB, T>>>(g, 0);
        // step 2: gates = r @ WihR^T + constvec ; LSTM ; attention -> z
        k_gates2<<<dim3(G4 / 64, NB / 64), T>>>(Wih);
        k_lstm2<<<(NB * D6) / T, T>>>(g);
        k_escore<<<warpNodeBlk, T>>>(g, 1, batch[g]);
        k_attn<<<NB, T>>>(g, 1);
    }

    // MLP head
    k_mlp1<<<(NB * 256 * 32) / T, T>>>(Wp1, bp1);
    k_mlp2<<<(NB * 128 * 32) / T, T>>>(Wp2, bp2);
    k_final<<<1, T>>>(Wp3, bp3, out);
}

// round 3
// speedup vs baseline: 1.4211x; 1.4211x over previous
#include <cuda_runtime.h>

#define NN   8192      // nodes per graph
#define NE   131072    // edges per graph
#define NB   256       // batches
#define NHF  128       // GCN hidden
#define FIN  64        // input features
#define H3   384       // 3*NHF
#define D6   768       // set2set channel dim
#define D12  1536
#define G4   3072      // 4*D6

// ---------------- scratch ----------------
__device__ __align__(16) float g_h[2][NN * H3];
__device__ __align__(16) float g_x[2][NN * D6];
__device__ __align__(16) float g_xw[NN * NHF];
__device__ float g_deg[NN];
__device__ int   g_cnt[NN];
__device__ int   g_cursor[NN];
__device__ int   g_rowptr[NN + 1];
__device__ int   g_csrc[NE];
__device__ float g_cnrm[NE];
__device__ float g_dinv[2][NN];
__device__ int   g_starts[2][NB + 1];
__device__ float g_hv[D6];
__device__ float g_cv[D6];
__device__ float g_cvec[G4];
__device__ float g_e[NN];
__device__ __align__(16) float g_rb[NB * D6];
__device__ __align__(16) float g_gates[NB * G4];
__device__ __align__(16) float g_hb[NB * D6];
__device__ __align__(16) float g_z[NB * G4];
__device__ __align__(16) float g_z1pre[NB * 256];
__device__ __align__(16) float g_z1[NB * 256];
__device__ __align__(16) float g_z2[NB * 128];

__device__ __forceinline__ float wredsum(float v) {
#pragma unroll
    for (int o = 16; o; o >>= 1) v += __shfl_xor_sync(0xffffffffu, v, o);
    return v;
}
__device__ __forceinline__ float sgm(float x) { return 1.f / (1.f + expf(-x)); }

// ---------------- CSR build ----------------
__global__ void k_zero_cnt() {
    int i = blockIdx.x * blockDim.x + threadIdx.x;
    if (i < NN) { g_cnt[i] = 0; g_deg[i] = 0.f; }
}
__global__ void k_count(const int* __restrict__ ei, const float* __restrict__ ew) {
    int e = blockIdx.x * blockDim.x + threadIdx.x;
    if (e < NE) {
        int d = ei[NE + e];
        atomicAdd(&g_cnt[d], 1);
        atomicAdd(&g_deg[d], ew[e]);
    }
}
__global__ void k_dinv(int gidx) {
    int i = blockIdx.x * blockDim.x + threadIdx.x;
    if (i < NN) g_dinv[gidx][i] = rsqrtf(g_deg[i] + 1.0f);
}
// single block, 1024 threads, 8 elems each: exclusive scan -> rowptr, cursor
__global__ void k_scan() {
    __shared__ int part[1024];
    int t = threadIdx.x;
    int base = t * 8;
    int loc[8], s = 0;
#pragma unroll
    for (int i = 0; i < 8; i++) { loc[i] = s; s += g_cnt[base + i]; }
    part[t] = s;
    __syncthreads();
    for (int o = 1; o < 1024; o <<= 1) {
        int v = (t >= o) ? part[t - o] : 0;
        __syncthreads();
        part[t] += v;
        __syncthreads();
    }
    int off = (t > 0) ? part[t - 1] : 0;
#pragma unroll
    for (int i = 0; i < 8; i++) {
        g_rowptr[base + i] = off + loc[i];
        g_cursor[base + i] = off + loc[i];
    }
    if (t == 1023) g_rowptr[NN] = part[1023];
}
__global__ void k_fill(const int* __restrict__ ei, const float* __restrict__ ew, int gidx) {
    int e = blockIdx.x * blockDim.x + threadIdx.x;
    if (e >= NE) return;
    int s = ei[e], d = ei[NE + e];
    int pos = atomicAdd(&g_cursor[d], 1);
    g_csrc[pos] = s;
    g_cnrm[pos] = g_dinv[gidx][s] * ew[e] * g_dinv[gidx][d];
}

// ---------------- tiled GEMM: g_xw[8192,128] = X[8192,K] @ W[K,128] ----------------
// X resolved DEVICE-SIDE: either external input (layer 0) or g_h[gidx] + srcoff.
__global__ void k_gemm_xw(const float* __restrict__ Xext, int useExt, int gidx, int srcoff,
                          int ldx, int K, const float* __restrict__ W) {
    __shared__ float As[16][64];
    __shared__ float Bs[16][68];
    const float* X = useExt ? Xext : (g_h[gidx] + srcoff);
    int tid = threadIdx.x, tx = tid & 15, ty = tid >> 4;
    int colBase = blockIdx.x * 64, rowBase = blockIdx.y * 64;
    float acc[4][4] = {};
    for (int k0 = 0; k0 < K; k0 += 16) {
#pragma unroll
        for (int l = 0; l < 4; l++) {
            int idx = tid + l * 256;
            int m = idx >> 4, kk = idx & 15;
            As[kk][m] = X[(size_t)(rowBase + m) * ldx + k0 + kk];
            Bs[kk][m] = W[(size_t)(k0 + kk) * NHF + colBase + m];
        }
        __syncthreads();
#pragma unroll
        for (int kk = 0; kk < 16; kk++) {
            float av[4], bv[4];
#pragma unroll
            for (int i = 0; i < 4; i++) av[i] = As[kk][ty * 4 + i];
#pragma unroll
            for (int j = 0; j < 4; j++) bv[j] = Bs[kk][tx * 4 + j];
#pragma unroll
            for (int i = 0; i < 4; i++)
#pragma unroll
                for (int j = 0; j < 4; j++) acc[i][j] += av[i] * bv[j];
        }
        __syncthreads();
    }
#pragma unroll
    for (int i = 0; i < 4; i++)
#pragma unroll
        for (int j = 0; j < 4; j++)
            g_xw[(size_t)(rowBase + ty * 4 + i) * NHF + colBase + tx * 4 + j] = acc[i][j];
}

// ---------------- fused GCN aggregation: gather + bias + self-loop + leaky ----------------
__global__ void k_gcn_gather(int gidx, int off, const float* __restrict__ bias) {
    int n = blockIdx.x * 8 + (threadIdx.x >> 5);
    int lane = threadIdx.x & 31;
    if (n >= NN) return;
    const float4* xw4 = (const float4*)g_xw;
    float di = g_dinv[gidx][n];
    float sn = di * di;
    float4 bb = ((const float4*)bias)[lane];
    float4 sv = xw4[(size_t)n * 32 + lane];
    float ax = bb.x + sn * sv.x, ay = bb.y + sn * sv.y;
    float az = bb.z + sn * sv.z, aw = bb.w + sn * sv.w;
    int e0 = g_rowptr[n], e1 = g_rowptr[n + 1];
    for (int e = e0; e < e1; e++) {
        int s = g_csrc[e];
        float nm = g_cnrm[e];
        float4 v = xw4[(size_t)s * 32 + lane];
        ax += nm * v.x; ay += nm * v.y; az += nm * v.z; aw += nm * v.w;
    }
    ax = (ax >= 0.f) ? ax : 0.2f * ax;
    ay = (ay >= 0.f) ? ay : 0.2f * ay;
    az = (az >= 0.f) ? az : 0.2f * az;
    aw = (aw >= 0.f) ? aw : 0.2f * aw;
    float4* o = (float4*)(g_h[gidx] + (size_t)n * H3 + off);
    o[lane] = make_float4(ax, ay, az, aw);
}

// ---------------- L2 normalize ----------------
__global__ void k_l2(int gidx) {
    int warp = blockIdx.x * 8 + (threadIdx.x >> 5);
    int lane = threadIdx.x & 31;
    if (warp >= NN) return;
    const float* hr = g_h[gidx] + (size_t)warp * H3;
    float ss = 0.f;
#pragma unroll
    for (int t = 0; t < 12; t++) { float v = hr[lane + 32 * t]; ss += v * v; }
    ss = wredsum(ss);
    float inv = 1.f / fmaxf(sqrtf(ss), 1e-12f);
    float* xr = g_x[gidx] + (size_t)warp * D6;
#pragma unroll
    for (int t = 0; t < 12; t++) xr[lane + 32 * t] = hr[lane + 32 * t] * inv;
}

// ---------------- segment starts ----------------
__global__ void k_starts(const int* __restrict__ batch, int gidx) {
    int n = blockIdx.x * blockDim.x + threadIdx.x;
    if (n >= NN) return;
    int b = batch[n];
    if (n == 0) {
        for (int bb = 0; bb <= b; bb++) g_starts[gidx][bb] = 0;
    } else {
        int pb = batch[n - 1];
        if (pb != b) for (int bb = pb + 1; bb <= b; bb++) g_starts[gidx][bb] = n;
    }
    if (n == NN - 1) for (int bb = b + 1; bb <= NB; bb++) g_starts[gidx][bb] = NN;
}

// ---------------- block-diagonal interaction ----------------
__global__ void k_interact() {
    int b = blockIdx.x;
    int s1 = g_starts[0][b], e1 = g_starts[0][b + 1];
    int s2 = g_starts[1][b], e2 = g_starts[1][b + 1];
    int n1 = e1 - s1, n2 = e2 - s2, tot = n1 + n2;
    int lane = threadIdx.x & 31, w = threadIdx.x >> 5;
    for (int t = w; t < tot; t += 8) {
        const float *src, *oth;
        float* out;
        int row, obase, ocnt;
        if (t < n1) { row = s1 + t;        src = g_x[0]; oth = g_x[1]; obase = s2; ocnt = n2; out = g_x[0]; }
        else        { row = s2 + (t - n1); src = g_x[1]; oth = g_x[0]; obase = s1; ocnt = n1; out = g_x[1]; }
        const float* sr = src + (size_t)row * D6;
        float sv[12], acc[12];
#pragma unroll
        for (int q = 0; q < 12; q++) { sv[q] = sr[lane + 32 * q]; acc[q] = 0.f; }
        for (int jj = 0; jj < ocnt; jj++) {
            const float* vr = oth + (size_t)(obase + jj) * D6;
            float vv[12], p = 0.f;
#pragma unroll
            for (int q = 0; q < 12; q++) { vv[q] = vr[lane + 32 * q]; p += sv[q] * vv[q]; }
            p = wredsum(p);
#pragma unroll
            for (int q = 0; q < 12; q++) acc[q] += p * vv[q];
        }
        float* orow = out + (size_t)row * D6 + H3;
#pragma unroll
        for (int q = 0; q < 12; q++) orow[lane + 32 * q] = acc[q];
    }
}

// ---------------- Set2Set ----------------
__global__ void k_lstm1(const float* __restrict__ bih, const float* __restrict__ bhh) {
    int j = blockIdx.x * blockDim.x + threadIdx.x;
    if (j >= D6) return;
    float gi = bih[j] + bhh[j];
    float gg = bih[2 * D6 + j] + bhh[2 * D6 + j];
    float go = bih[3 * D6 + j] + bhh[3 * D6 + j];
    float c = sgm(gi) * tanhf(gg);
    g_cv[j] = c;
    g_hv[j] = sgm(go) * tanhf(c);
}

__global__ void k_escore(int gidx, int useHb, const int* __restrict__ batch) {
    int warp = blockIdx.x * 8 + (threadIdx.x >> 5);
    int lane = threadIdx.x & 31;
    if (warp >= NN) return;
    const float* xr = g_x[gidx] + (size_t)warp * D6;
    const float* hr = useHb ? (g_hb + (size_t)batch[warp] * D6) : g_hv;
    float p = 0.f;
#pragma unroll
    for (int t = 0; t < 24; t++) p += xr[lane + 32 * t] * hr[lane + 32 * t];
    p = wredsum(p);
    if (lane == 0) g_e[warp] = p;
}

__global__ void k_attn(int gidx, int mode) {
    int b = blockIdx.x;
    int s = g_starts[gidx][b], e = g_starts[gidx][b + 1];
    int tid = threadIdx.x;
    float* rout = (mode == 0) ? (g_rb + (size_t)b * D6)
                              : (g_z + (size_t)b * G4 + (gidx ? D12 : 0) + D6);
    if (e <= s) {
        for (int f = tid; f < D6; f += 256) rout[f] = 0.f;
        return;
    }
    __shared__ float red[256];
    __shared__ float ee[256];
    const float* x = g_x[gidx];
    float lm = -3.4e38f;
    for (int n = s + tid; n < e; n += 256) lm = fmaxf(lm, g_e[n]);
    red[tid] = lm; __syncthreads();
    for (int o = 128; o > 0; o >>= 1) { if (tid < o) red[tid] = fmaxf(red[tid], red[tid + o]); __syncthreads(); }
    float m = red[0]; __syncthreads();
    float ls = 0.f;
    for (int n = s + tid; n < e; n += 256) ls += expf(g_e[n] - m);
    red[tid] = ls; __syncthreads();
    for (int o = 128; o > 0; o >>= 1) { if (tid < o) red[tid] += red[tid + o]; __syncthreads(); }
    float S = red[0]; __syncthreads();
    float a0 = 0.f, a1 = 0.f, a2 = 0.f;
    for (int base = s; base < e; base += 256) {
        int cnt = min(256, e - base);
        if (tid < cnt) ee[tid] = expf(g_e[base + tid] - m);
        __syncthreads();
        for (int t = 0; t < cnt; t++) {
            float w = ee[t];
            const float* xr = x + (size_t)(base + t) * D6;
            a0 += w * xr[tid];
            a1 += w * xr[tid + 256];
            a2 += w * xr[tid + 512];
        }
        __syncthreads();
    }
    float inv = 1.f / S;
    rout[tid] = a0 * inv;
    rout[tid + 256] = a1 * inv;
    rout[tid + 512] = a2 * inv;
}

__global__ void k_cvec(const float* __restrict__ Wih, const float* __restrict__ Whh,
                       const float* __restrict__ bih, const float* __restrict__ bhh) {
    int g = blockIdx.x * 8 + (threadIdx.x >> 5);
    int lane = threadIdx.x & 31;
    if (g >= G4) return;
    const float* wi = Wih + (size_t)g * D12;
    const float* wh = Whh + (size_t)g * D6;
    float p = 0.f;
#pragma unroll
    for (int t = 0; t < 24; t++) {
        int k = lane + 32 * t;
        p += g_hv[k] * (wi[k] + wh[k]);
    }
    p = wredsum(p);
    if (lane == 0) g_cvec[g] = bih[g] + bhh[g] + p;
}

// gates2 = g_rb @ WihR^T + cvec
__global__ void k_gates2(const float* __restrict__ Wih) {
    __shared__ float As[16][64];
    __shared__ float Bs[16][68];
    int tid = threadIdx.x, tx = tid & 15, ty = tid >> 4;
    int colBase = blockIdx.x * 64, rowBase = blockIdx.y * 64;
    const float* B = Wih + D6;
    float acc[4][4] = {};
    for (int k0 = 0; k0 < D6; k0 += 16) {
#pragma unroll
        for (int l = 0; l < 4; l++) {
            int idx = tid + l * 256;
            int m = idx >> 4, kk = idx & 15;
            As[kk][m] = g_rb[(size_t)(rowBase + m) * D6 + k0 + kk];
            Bs[kk][m] = B[(size_t)(colBase + m) * D12 + k0 + kk];
        }
        __syncthreads();
#pragma unroll
        for (int kk = 0; kk < 16; kk++) {
            float av[4], bv[4];
#pragma unroll
            for (int i = 0; i < 4; i++) av[i] = As[kk][ty * 4 + i];
#pragma unroll
            for (int j = 0; j < 4; j++) bv[j] = Bs[kk][tx * 4 + j];
#pragma unroll
            for (int i = 0; i < 4; i++)
#pragma unroll
                for (int j = 0; j < 4; j++) acc[i][j] += av[i] * bv[j];
        }
        __syncthreads();
    }
#pragma unroll
    for (int i = 0; i < 4; i++) {
        int row = rowBase + ty * 4 + i;
#pragma unroll
        for (int j = 0; j < 4; j++) {
            int col = colBase + tx * 4 + j;
            g_gates[(size_t)row * G4 + col] = acc[i][j] + g_cvec[col];
        }
    }
}

__global__ void k_lstm2(int gidx) {
    int i = blockIdx.x * blockDim.x + threadIdx.x;
    if (i >= NB * D6) return;
    int b = i / D6, j = i - b * D6;
    const float* g = g_gates + (size_t)b * G4;
    float gi = g[j], gf = g[D6 + j], gg = g[2 * D6 + j], go = g[3 * D6 + j];
    float c = sgm(gf) * g_cv[j] + sgm(gi) * tanhf(gg);
    float h = sgm(go) * tanhf(c);
    g_hb[i] = h;
    g_z[(size_t)b * G4 + (gidx ? D12 : 0) + j] = h;
}

// ---------------- MLP head ----------------
__global__ void k_zero_z1pre() {
    int i = blockIdx.x * blockDim.x + threadIdx.x;
    if (i < NB * 256) g_z1pre[i] = 0.f;
}
__global__ void k_mlp1_gemm(const float* __restrict__ Wp1) {
    __shared__ float As[16][64];
    __shared__ float Bs[16][68];
    int tid = threadIdx.x, tx = tid & 15, ty = tid >> 4;
    int colBase = blockIdx.x * 64, rowBase = blockIdx.y * 64;
    int kBase = blockIdx.z * 128;
    float acc[4][4] = {};
    for (int k0 = 0; k0 < 128; k0 += 16) {
#pragma unroll
        for (int l = 0; l < 4; l++) {
            int idx = tid + l * 256;
            int m = idx >> 4, kk = idx & 15;
            As[kk][m] = g_z[(size_t)(rowBase + m) * G4 + kBase + k0 + kk];
            Bs[kk][m] = Wp1[(size_t)(colBase + m) * G4 + kBase + k0 + kk];
        }
        __syncthreads();
#pragma unroll
        for (int kk = 0; kk < 16; kk++) {
            float av[4], bv[4];
#pragma unroll
            for (int i = 0; i < 4; i++) av[i] = As[kk][ty * 4 + i];
#pragma unroll
            for (int j = 0; j < 4; j++) bv[j] = Bs[kk][tx * 4 + j];
#pragma unroll
            for (int i = 0; i < 4; i++)
#pragma unroll
                for (int j = 0; j < 4; j++) acc[i][j] += av[i] * bv[j];
        }
        __syncthreads();
    }
#pragma unroll
    for (int i = 0; i < 4; i++)
#pragma unroll
        for (int j = 0; j < 4; j++)
            atomicAdd(&g_z1pre[(size_t)(rowBase + ty * 4 + i) * 256 + colBase + tx * 4 + j],
                      acc[i][j]);
}
__global__ void k_relu1(const float* __restrict__ bp1) {
    int i = blockIdx.x * blockDim.x + threadIdx.x;
    if (i >= NB * 256) return;
    int o = i & 255;
    g_z1[i] = fmaxf(g_z1pre[i] + bp1[o], 0.f);
}
__global__ void k_mlp2(const float* __restrict__ Wp2, const float* __restrict__ bp2) {
    int gw = (blockIdx.x * blockDim.x + threadIdx.x) >> 5;
    int lane = threadIdx.x & 31;
    if (gw >= NB * 128) return;
    int b = gw >> 7, o = gw & 127;
    const float4* a = (const float4*)(g_z1 + (size_t)b * 256);
    const float4* w = (const float4*)(Wp2 + (size_t)o * 256);
    float p = 0.f;
#pragma unroll
    for (int t = lane; t < 64; t += 32) {
        float4 x = a[t], y = w[t];
        p += x.x * y.x + x.y * y.y + x.z * y.z + x.w * y.w;
    }
    p = wredsum(p);
    if (lane == 0) g_z2[(size_t)b * 128 + o] = fmaxf(p + bp2[o], 0.f);
}
__global__ void k_final(const float* __restrict__ Wp3, const float* __restrict__ bp3,
                        float* __restrict__ out) {
    int b = blockIdx.x * blockDim.x + threadIdx.x;
    if (b >= NB) return;
    float p = bp3[0];
#pragma unroll 16
    for (int k = 0; k < 128; k++) p += g_z2[(size_t)b * 128 + k] * Wp3[k];
    out[b] = 1.f / (1.f + expf(-p));
}

// ---------------- launch sequence ----------------
extern "C" void kernel_launch(void* const* d_in, const int* in_sizes, int n_in,
                              void* d_out, int out_size) {
    const float* feat[2] = { (const float*)d_in[0], (const float*)d_in[1] };
    const float* ea[2]   = { (const float*)d_in[2], (const float*)d_in[3] };
    const float* W[3]    = { (const float*)d_in[4], (const float*)d_in[6], (const float*)d_in[8] };
    const float* bW[3]   = { (const float*)d_in[5], (const float*)d_in[7], (const float*)d_in[9] };
    const float* Wih = (const float*)d_in[10];
    const float* bih = (const float*)d_in[11];
    const float* Whh = (const float*)d_in[12];
    const float* bhh = (const float*)d_in[13];
    const float* Wp1 = (const float*)d_in[14];
    const float* bp1 = (const float*)d_in[15];
    const float* Wp2 = (const float*)d_in[16];
    const float* bp2 = (const float*)d_in[17];
    const float* Wp3 = (const float*)d_in[18];
    const float* bp3 = (const float*)d_in[19];
    const int* ei[2]    = { (const int*)d_in[20], (const int*)d_in[21] };
    const int* batch[2] = { (const int*)d_in[22], (const int*)d_in[23] };
    float* out = (float*)d_out;

    const int T = 256;
    const int nodeBlk = NN / T;            // 32
    const int warpNodeBlk = NN / 8;        // 1024
    const int edgeBlk = NE / T;            // 512

    for (int g = 0; g < 2; g++) {
        // CSR build (once per graph, reused by all 3 layers)
        k_zero_cnt<<<nodeBlk, T>>>();
        k_count<<<edgeBlk, T>>>(ei[g], ea[g]);
        k_dinv<<<nodeBlk, T>>>(g);
        k_scan<<<1, 1024>>>();
        k_fill<<<edgeBlk, T>>>(ei[g], ea[g], g);
        // 3 GCN layers: GEMM then fused gather.
        // NOTE: g_h pointer is resolved DEVICE-SIDE via (useExt, gidx, srcoff);
        // passing &g_h[...] from host reads the host shadow symbol (ATS!) — silent zeros.
        for (int l = 0; l < 3; l++) {
            if (l == 0)
                k_gemm_xw<<<dim3(2, NN / 64), T>>>(feat[g], 1, g, 0, FIN, FIN, W[l]);
            else
                k_gemm_xw<<<dim3(2, NN / 64), T>>>(nullptr, 0, g, (l - 1) * NHF, H3, NHF, W[l]);
            k_gcn_gather<<<warpNodeBlk, T>>>(g, l * NHF, bW[l]);
        }
        k_l2<<<warpNodeBlk, T>>>(g);
    }

    k_starts<<<nodeBlk, T>>>(batch[0], 0);
    k_starts<<<nodeBlk, T>>>(batch[1], 1);
    k_interact<<<NB, T>>>();

    k_lstm1<<<(D6 + T - 1) / T, T>>>(bih, bhh);
    k_cvec<<<G4 / 8, T>>>(Wih, Whh, bih, bhh);

    for (int g = 0; g < 2; g++) {
        k_escore<<<warpNodeBlk, T>>>(g, 0, batch[g]);
        k_attn<<<NB, T>>>(g, 0);
        k_gates2<<<dim3(G4 / 64, NB / 64), T>>>(Wih);
        k_lstm2<<<(NB * D6) / T, T>>>(g);
        k_escore<<<warpNodeBlk, T>>>(g, 1, batch[g]);
        k_attn<<<NB, T>>>(g, 1);
    }

    k_zero_z1pre<<<(NB * 256) / T, T>>>();
    k_mlp1_gemm<<<dim3(4, 4, 24), T>>>(Wp1);
    k_relu1<<<(NB * 256) / T, T>>>(bp1);
    k_mlp2<<<(NB * 128 * 32) / T, T>>>(Wp2, bp2);
    k_final<<<1, T>>>(Wp3, bp3, out);
}

// round 4
// speedup vs baseline: 1.5823x; 1.1135x over previous
#include <cuda_runtime.h>

#define NN   8192
#define NE   131072
#define NB   256
#define NHF  128
#define FIN  64
#define H3   384
#define D6   768
#define D12  1536
#define G4   3072

// ---------------- scratch (per-graph duplicated for stream overlap) ----------------
__device__ __align__(16) float g_h[2][NN * H3];
__device__ __align__(16) float g_x[2][NN * D6];
__device__ __align__(16) float g_xw[2][NN * NHF];
__device__ float g_deg[2][NN];
__device__ int   g_cnt[2][NN];
__device__ int   g_cursor[2][NN];
__device__ int   g_rowptr[2][NN + 1];
__device__ int   g_csrc[2][NE];
__device__ float g_cnrm[2][NE];
__device__ float g_dinv[2][NN];
__device__ int   g_starts[2][NB + 1];
__device__ float g_hv[D6];
__device__ float g_cv[D6];
__device__ float g_cvec[G4];
__device__ float g_e[2][NN];
__device__ __align__(16) float g_rb[2][NB * D6];
__device__ __align__(16) float g_gates[2][NB * G4];
__device__ __align__(16) float g_hb[2][NB * D6];
__device__ __align__(16) float g_z[NB * G4];
__device__ __align__(16) float g_z1pre[NB * 256];
__device__ __align__(16) float g_z1[NB * 256];
__device__ __align__(16) float g_z2[NB * 128];

__device__ __forceinline__ float wredsum(float v) {
#pragma unroll
    for (int o = 16; o; o >>= 1) v += __shfl_xor_sync(0xffffffffu, v, o);
    return v;
}
__device__ __forceinline__ float sgm(float x) { return 1.f / (1.f + expf(-x)); }

// ---------------- CSR build ----------------
__global__ void k_zero_cnt(int g) {
    int i = blockIdx.x * blockDim.x + threadIdx.x;
    if (i < NN) { g_cnt[g][i] = 0; g_deg[g][i] = 0.f; }
}
__global__ void k_count(const int* __restrict__ ei, const float* __restrict__ ew, int g) {
    int e = blockIdx.x * blockDim.x + threadIdx.x;
    if (e < NE) {
        int d = ei[NE + e];
        atomicAdd(&g_cnt[g][d], 1);
        atomicAdd(&g_deg[g][d], ew[e]);
    }
}
__global__ void k_dinv(int g) {
    int i = blockIdx.x * blockDim.x + threadIdx.x;
    if (i < NN) g_dinv[g][i] = rsqrtf(g_deg[g][i] + 1.0f);
}
// warp-shuffle hierarchical scan: 1024 threads x 8 elems, 2 syncs
__global__ void k_scan(int g) {
    __shared__ int wsum[32];
    int t = threadIdx.x, lane = t & 31, w = t >> 5;
    int base = t * 8;
    int loc[8], s = 0;
#pragma unroll
    for (int i = 0; i < 8; i++) { loc[i] = s; s += g_cnt[g][base + i]; }
    int x = s;
#pragma unroll
    for (int o = 1; o < 32; o <<= 1) {
        int y = __shfl_up_sync(0xffffffffu, x, o);
        if (lane >= o) x += y;
    }
    if (lane == 31) wsum[w] = x;
    __syncthreads();
    if (w == 0) {
        int y = wsum[lane];
#pragma unroll
        for (int o = 1; o < 32; o <<= 1) {
            int z = __shfl_up_sync(0xffffffffu, y, o);
            if (lane >= o) y += z;
        }
        wsum[lane] = y;
    }
    __syncthreads();
    int off = x - s + ((w > 0) ? wsum[w - 1] : 0);
#pragma unroll
    for (int i = 0; i < 8; i++) {
        g_rowptr[g][base + i] = off + loc[i];
        g_cursor[g][base + i] = off + loc[i];
    }
    if (t == 1023) g_rowptr[g][NN] = wsum[31];
}
__global__ void k_fill(const int* __restrict__ ei, const float* __restrict__ ew, int g) {
    int e = blockIdx.x * blockDim.x + threadIdx.x;
    if (e >= NE) return;
    int s = ei[e], d = ei[NE + e];
    int pos = atomicAdd(&g_cursor[g][d], 1);
    g_csrc[g][pos] = s;
    g_cnrm[g][pos] = g_dinv[g][s] * ew[e] * g_dinv[g][d];
}

// ---------------- tiled GEMM: g_xw[g] = X[8192,K] @ W[K,128] ----------------
__global__ void k_gemm_xw(const float* __restrict__ Xext, int useExt, int g, int srcoff,
                          int ldx, int K, const float* __restrict__ W) {
    __shared__ float As[16][64];
    __shared__ float Bs[16][68];
    const float* X = useExt ? Xext : (g_h[g] + srcoff);
    int tid = threadIdx.x, tx = tid & 15, ty = tid >> 4;
    int colBase = blockIdx.x * 64, rowBase = blockIdx.y * 64;
    float acc[4][4] = {};
    for (int k0 = 0; k0 < K; k0 += 16) {
#pragma unroll
        for (int l = 0; l < 4; l++) {
            int idx = tid + l * 256;
            int m = idx >> 4, kk = idx & 15;
            As[kk][m] = X[(size_t)(rowBase + m) * ldx + k0 + kk];
            Bs[kk][m] = W[(size_t)(k0 + kk) * NHF + colBase + m];
        }
        __syncthreads();
#pragma unroll
        for (int kk = 0; kk < 16; kk++) {
            float av[4], bv[4];
#pragma unroll
            for (int i = 0; i < 4; i++) av[i] = As[kk][ty * 4 + i];
#pragma unroll
            for (int j = 0; j < 4; j++) bv[j] = Bs[kk][tx * 4 + j];
#pragma unroll
            for (int i = 0; i < 4; i++)
#pragma unroll
                for (int j = 0; j < 4; j++) acc[i][j] += av[i] * bv[j];
        }
        __syncthreads();
    }
#pragma unroll
    for (int i = 0; i < 4; i++)
#pragma unroll
        for (int j = 0; j < 4; j++)
            g_xw[g][(size_t)(rowBase + ty * 4 + i) * NHF + colBase + tx * 4 + j] = acc[i][j];
}

// ---------------- fused GCN aggregation ----------------
__global__ void k_gcn_gather(int g, int off, const float* __restrict__ bias) {
    int n = blockIdx.x * 8 + (threadIdx.x >> 5);
    int lane = threadIdx.x & 31;
    if (n >= NN) return;
    const float4* xw4 = (const float4*)g_xw[g];
    float di = g_dinv[g][n];
    float sn = di * di;
    float4 bb = ((const float4*)bias)[lane];
    float4 sv = xw4[(size_t)n * 32 + lane];
    float ax = bb.x + sn * sv.x, ay = bb.y + sn * sv.y;
    float az = bb.z + sn * sv.z, aw = bb.w + sn * sv.w;
    int e0 = g_rowptr[g][n], e1 = g_rowptr[g][n + 1];
    for (int e = e0; e < e1; e++) {
        int s = g_csrc[g][e];
        float nm = g_cnrm[g][e];
        float4 v = xw4[(size_t)s * 32 + lane];
        ax += nm * v.x; ay += nm * v.y; az += nm * v.z; aw += nm * v.w;
    }
    ax = (ax >= 0.f) ? ax : 0.2f * ax;
    ay = (ay >= 0.f) ? ay : 0.2f * ay;
    az = (az >= 0.f) ? az : 0.2f * az;
    aw = (aw >= 0.f) ? aw : 0.2f * aw;
    float4* o = (float4*)(g_h[g] + (size_t)n * H3 + off);
    o[lane] = make_float4(ax, ay, az, aw);
}

// ---------------- L2 normalize ----------------
__global__ void k_l2(int g) {
    int warp = blockIdx.x * 8 + (threadIdx.x >> 5);
    int lane = threadIdx.x & 31;
    if (warp >= NN) return;
    const float* hr = g_h[g] + (size_t)warp * H3;
    float ss = 0.f;
#pragma unroll
    for (int t = 0; t < 12; t++) { float v = hr[lane + 32 * t]; ss += v * v; }
    ss = wredsum(ss);
    float inv = 1.f / fmaxf(sqrtf(ss), 1e-12f);
    float* xr = g_x[g] + (size_t)warp * D6;
#pragma unroll
    for (int t = 0; t < 12; t++) xr[lane + 32 * t] = hr[lane + 32 * t] * inv;
}

// ---------------- segment starts ----------------
__global__ void k_starts(const int* __restrict__ batch, int g) {
    int n = blockIdx.x * blockDim.x + threadIdx.x;
    if (n >= NN) return;
    int b = batch[n];
    if (n == 0) {
        for (int bb = 0; bb <= b; bb++) g_starts[g][bb] = 0;
    } else {
        int pb = batch[n - 1];
        if (pb != b) for (int bb = pb + 1; bb <= b; bb++) g_starts[g][bb] = n;
    }
    if (n == NN - 1) for (int bb = b + 1; bb <= NB; bb++) g_starts[g][bb] = NN;
}

// ---------------- block-diagonal interaction ----------------
__global__ void k_interact() {
    int b = blockIdx.x;
    int s1 = g_starts[0][b], e1 = g_starts[0][b + 1];
    int s2 = g_starts[1][b], e2 = g_starts[1][b + 1];
    int n1 = e1 - s1, n2 = e2 - s2, tot = n1 + n2;
    int lane = threadIdx.x & 31, w = threadIdx.x >> 5;
    for (int t = w; t < tot; t += 8) {
        const float *src, *oth;
        float* out;
        int row, obase, ocnt;
        if (t < n1) { row = s1 + t;        src = g_x[0]; oth = g_x[1]; obase = s2; ocnt = n2; out = g_x[0]; }
        else        { row = s2 + (t - n1); src = g_x[1]; oth = g_x[0]; obase = s1; ocnt = n1; out = g_x[1]; }
        const float* sr = src + (size_t)row * D6;
        float sv[12], acc[12];
#pragma unroll
        for (int q = 0; q < 12; q++) { sv[q] = sr[lane + 32 * q]; acc[q] = 0.f; }
        for (int jj = 0; jj < ocnt; jj++) {
            const float* vr = oth + (size_t)(obase + jj) * D6;
            float vv[12], p = 0.f;
#pragma unroll
            for (int q = 0; q < 12; q++) { vv[q] = vr[lane + 32 * q]; p += sv[q] * vv[q]; }
            p = wredsum(p);
#pragma unroll
            for (int q = 0; q < 12; q++) acc[q] += p * vv[q];
        }
        float* orow = out + (size_t)row * D6 + H3;
#pragma unroll
        for (int q = 0; q < 12; q++) orow[lane + 32 * q] = acc[q];
    }
}

// ---------------- Set2Set ----------------
__global__ void k_lstm1(const float* __restrict__ bih, const float* __restrict__ bhh) {
    int j = blockIdx.x * blockDim.x + threadIdx.x;
    if (j >= D6) return;
    float gi = bih[j] + bhh[j];
    float gg = bih[2 * D6 + j] + bhh[2 * D6 + j];
    float go = bih[3 * D6 + j] + bhh[3 * D6 + j];
    float c = sgm(gi) * tanhf(gg);
    g_cv[j] = c;
    g_hv[j] = sgm(go) * tanhf(c);
}

__global__ void k_escore(int g, int useHb, const int* __restrict__ batch) {
    int warp = blockIdx.x * 8 + (threadIdx.x >> 5);
    int lane = threadIdx.x & 31;
    if (warp >= NN) return;
    const float* xr = g_x[g] + (size_t)warp * D6;
    const float* hr = useHb ? (g_hb[g] + (size_t)batch[warp] * D6) : g_hv;
    float p = 0.f;
#pragma unroll
    for (int t = 0; t < 24; t++) p += xr[lane + 32 * t] * hr[lane + 32 * t];
    p = wredsum(p);
    if (lane == 0) g_e[g][warp] = p;
}

__global__ void k_attn(int g, int mode) {
    int b = blockIdx.x;
    int s = g_starts[g][b], e = g_starts[g][b + 1];
    int tid = threadIdx.x;
    float* rout = (mode == 0) ? (g_rb[g] + (size_t)b * D6)
                              : (g_z + (size_t)b * G4 + (g ? D12 : 0) + D6);
    if (e <= s) {
        for (int f = tid; f < D6; f += 256) rout[f] = 0.f;
        return;
    }
    __shared__ float red[256];
    __shared__ float ee[256];
    const float* x = g_x[g];
    float lm = -3.4e38f;
    for (int n = s + tid; n < e; n += 256) lm = fmaxf(lm, g_e[g][n]);
    red[tid] = lm; __syncthreads();
    for (int o = 128; o > 0; o >>= 1) { if (tid < o) red[tid] = fmaxf(red[tid], red[tid + o]); __syncthreads(); }
    float m = red[0]; __syncthreads();
    float ls = 0.f;
    for (int n = s + tid; n < e; n += 256) ls += expf(g_e[g][n] - m);
    red[tid] = ls; __syncthreads();
    for (int o = 128; o > 0; o >>= 1) { if (tid < o) red[tid] += red[tid + o]; __syncthreads(); }
    float S = red[0]; __syncthreads();
    float a0 = 0.f, a1 = 0.f, a2 = 0.f;
    for (int base = s; base < e; base += 256) {
        int cnt = min(256, e - base);
        if (tid < cnt) ee[tid] = expf(g_e[g][base + tid] - m);
        __syncthreads();
        for (int t = 0; t < cnt; t++) {
            float w = ee[t];
            const float* xr = x + (size_t)(base + t) * D6;
            a0 += w * xr[tid];
            a1 += w * xr[tid + 256];
            a2 += w * xr[tid + 512];
        }
        __syncthreads();
    }
    float inv = 1.f / S;
    rout[tid] = a0 * inv;
    rout[tid + 256] = a1 * inv;
    rout[tid + 512] = a2 * inv;
}

__global__ void k_cvec(const float* __restrict__ Wih, const float* __restrict__ Whh,
                       const float* __restrict__ bih, const float* __restrict__ bhh) {
    int g = blockIdx.x * 8 + (threadIdx.x >> 5);
    int lane = threadIdx.x & 31;
    if (g >= G4) return;
    const float* wi = Wih + (size_t)g * D12;
    const float* wh = Whh + (size_t)g * D6;
    float p = 0.f;
#pragma unroll
    for (int t = 0; t < 24; t++) {
        int k = lane + 32 * t;
        p += g_hv[k] * (wi[k] + wh[k]);
    }
    p = wredsum(p);
    if (lane == 0) g_cvec[g] = bih[g] + bhh[g] + p;
}

// gates2[g] = g_rb[g] @ WihR^T + cvec   (64x128 tile, 4x8 micro)
__global__ void k_gates2(const float* __restrict__ Wih, int g) {
    __shared__ float As[16][64];
    __shared__ float Bs[16][136];
    int tid = threadIdx.x, tx = tid & 15, ty = tid >> 4;
    int colBase = blockIdx.x * 128, rowBase = blockIdx.y * 64;
    const float* A = g_rb[g];
    const float* B = Wih + D6;
    float acc[4][8] = {};
    for (int k0 = 0; k0 < D6; k0 += 16) {
#pragma unroll
        for (int l = 0; l < 4; l++) {
            int idx = tid + l * 256;
            int m = idx >> 4, kk = idx & 15;
            As[kk][m] = A[(size_t)(rowBase + m) * D6 + k0 + kk];
        }
#pragma unroll
        for (int l = 0; l < 8; l++) {
            int idx = tid + l * 256;
            int n = idx >> 4, kk = idx & 15;
            Bs[kk][n] = B[(size_t)(colBase + n) * D12 + k0 + kk];
        }
        __syncthreads();
#pragma unroll
        for (int kk = 0; kk < 16; kk++) {
            float av[4], bv[8];
#pragma unroll
            for (int i = 0; i < 4; i++) av[i] = As[kk][ty * 4 + i];
#pragma unroll
            for (int j = 0; j < 8; j++) bv[j] = Bs[kk][tx * 8 + j];
#pragma unroll
            for (int i = 0; i < 4; i++)
#pragma unroll
                for (int j = 0; j < 8; j++) acc[i][j] += av[i] * bv[j];
        }
        __syncthreads();
    }
#pragma unroll
    for (int i = 0; i < 4; i++) {
        int row = rowBase + ty * 4 + i;
#pragma unroll
        for (int j = 0; j < 8; j++) {
            int col = colBase + tx * 8 + j;
            g_gates[g][(size_t)row * G4 + col] = acc[i][j] + g_cvec[col];
        }
    }
}

__global__ void k_lstm2(int g) {
    int i = blockIdx.x * blockDim.x + threadIdx.x;
    if (i >= NB * D6) return;
    int b = i / D6, j = i - b * D6;
    const float* gt = g_gates[g] + (size_t)b * G4;
    float gi = gt[j], gf = gt[D6 + j], gg = gt[2 * D6 + j], go = gt[3 * D6 + j];
    float c = sgm(gf) * g_cv[j] + sgm(gi) * tanhf(gg);
    float h = sgm(go) * tanhf(c);
    g_hb[g][i] = h;
    g_z[(size_t)b * G4 + (g ? D12 : 0) + j] = h;
}

// ---------------- MLP head ----------------
__global__ void k_zero_z1pre() {
    int i = blockIdx.x * blockDim.x + threadIdx.x;
    if (i < NB * 256) g_z1pre[i] = 0.f;
}
__global__ void k_mlp1_gemm(const float* __restrict__ Wp1) {
    __shared__ float As[16][64];
    __shared__ float Bs[16][68];
    int tid = threadIdx.x, tx = tid & 15, ty = tid >> 4;
    int colBase = blockIdx.x * 64, rowBase = blockIdx.y * 64;
    int kBase = blockIdx.z * 128;
    float acc[4][4] = {};
    for (int k0 = 0; k0 < 128; k0 += 16) {
#pragma unroll
        for (int l = 0; l < 4; l++) {
            int idx = tid + l * 256;
            int m = idx >> 4, kk = idx & 15;
            As[kk][m] = g_z[(size_t)(rowBase + m) * G4 + kBase + k0 + kk];
            Bs[kk][m] = Wp1[(size_t)(colBase + m) * G4 + kBase + k0 + kk];
        }
        __syncthreads();
#pragma unroll
        for (int kk = 0; kk < 16; kk++) {
            float av[4], bv[4];
#pragma unroll
            for (int i = 0; i < 4; i++) av[i] = As[kk][ty * 4 + i];
#pragma unroll
            for (int j = 0; j < 4; j++) bv[j] = Bs[kk][tx * 4 + j];
#pragma unroll
            for (int i = 0; i < 4; i++)
#pragma unroll
                for (int j = 0; j < 4; j++) acc[i][j] += av[i] * bv[j];
        }
        __syncthreads();
    }
#pragma unroll
    for (int i = 0; i < 4; i++)
#pragma unroll
        for (int j = 0; j < 4; j++)
            atomicAdd(&g_z1pre[(size_t)(rowBase + ty * 4 + i) * 256 + colBase + tx * 4 + j],
                      acc[i][j]);
}
__global__ void k_relu1(const float* __restrict__ bp1) {
    int i = blockIdx.x * blockDim.x + threadIdx.x;
    if (i >= NB * 256) return;
    int o = i & 255;
    g_z1[i] = fmaxf(g_z1pre[i] + bp1[o], 0.f);
}
__global__ void k_mlp2(const float* __restrict__ Wp2, const float* __restrict__ bp2) {
    int gw = (blockIdx.x * blockDim.x + threadIdx.x) >> 5;
    int lane = threadIdx.x & 31;
    if (gw >= NB * 128) return;
    int b = gw >> 7, o = gw & 127;
    const float4* a = (const float4*)(g_z1 + (size_t)b * 256);
    const float4* w = (const float4*)(Wp2 + (size_t)o * 256);
    float p = 0.f;
#pragma unroll
    for (int t = lane; t < 64; t += 32) {
        float4 x = a[t], y = w[t];
        p += x.x * y.x + x.y * y.y + x.z * y.z + x.w * y.w;
    }
    p = wredsum(p);
    if (lane == 0) g_z2[(size_t)b * 128 + o] = fmaxf(p + bp2[o], 0.f);
}
__global__ void k_final(const float* __restrict__ Wp3, const float* __restrict__ bp3,
                        float* __restrict__ out) {
    int b = blockIdx.x * blockDim.x + threadIdx.x;
    if (b >= NB) return;
    float p = bp3[0];
#pragma unroll 16
    for (int k = 0; k < 128; k++) p += g_z2[(size_t)b * 128 + k] * Wp3[k];
    out[b] = 1.f / (1.f + expf(-p));
}

// ---------------- launch sequence (two-stream forked pipeline) ----------------
extern "C" void kernel_launch(void* const* d_in, const int* in_sizes, int n_in,
                              void* d_out, int out_size) {
    const float* feat[2] = { (const float*)d_in[0], (const float*)d_in[1] };
    const float* ea[2]   = { (const float*)d_in[2], (const float*)d_in[3] };
    const float* W[3]    = { (const float*)d_in[4], (const float*)d_in[6], (const float*)d_in[8] };
    const float* bW[3]   = { (const float*)d_in[5], (const float*)d_in[7], (const float*)d_in[9] };
    const float* Wih = (const float*)d_in[10];
    const float* bih = (const float*)d_in[11];
    const float* Whh = (const float*)d_in[12];
    const float* bhh = (const float*)d_in[13];
    const float* Wp1 = (const float*)d_in[14];
    const float* bp1 = (const float*)d_in[15];
    const float* Wp2 = (const float*)d_in[16];
    const float* bp2 = (const float*)d_in[17];
    const float* Wp3 = (const float*)d_in[18];
    const float* bp3 = (const float*)d_in[19];
    const int* ei[2]    = { (const int*)d_in[20], (const int*)d_in[21] };
    const int* batch[2] = { (const int*)d_in[22], (const int*)d_in[23] };
    float* out = (float*)d_out;

    // streams/events created once on the first (non-captured, correctness) call;
    // on capture calls they already exist. Host-side only — no device allocation.
    static cudaStream_t s1 = (cudaStream_t)0;
    static cudaEvent_t evA, evB, evC, evD;
    static bool inited = false;
    if (!inited) {
        cudaStreamCreateWithFlags(&s1, cudaStreamNonBlocking);
        cudaEventCreateWithFlags(&evA, cudaEventDisableTiming);
        cudaEventCreateWithFlags(&evB, cudaEventDisableTiming);
        cudaEventCreateWithFlags(&evC, cudaEventDisableTiming);
        cudaEventCreateWithFlags(&evD, cudaEventDisableTiming);
        inited = true;
    }
    cudaStream_t s0 = (cudaStream_t)0;
    const int T = 256;

    auto gcn_chain = [&](int g, cudaStream_t st) {
        k_zero_cnt<<<NN / T, T, 0, st>>>(g);
        k_count<<<NE / T, T, 0, st>>>(ei[g], ea[g], g);
        k_dinv<<<NN / T, T, 0, st>>>(g);
        k_scan<<<1, 1024, 0, st>>>(g);
        k_fill<<<NE / T, T, 0, st>>>(ei[g], ea[g], g);
        for (int l = 0; l < 3; l++) {
            if (l == 0)
                k_gemm_xw<<<dim3(2, NN / 64), T, 0, st>>>(feat[g], 1, g, 0, FIN, FIN, W[l]);
            else
                k_gemm_xw<<<dim3(2, NN / 64), T, 0, st>>>(nullptr, 0, g, (l - 1) * NHF, H3, NHF, W[l]);
            k_gcn_gather<<<NN / 8, T, 0, st>>>(g, l * NHF, bW[l]);
        }
        k_l2<<<NN / 8, T, 0, st>>>(g);
        k_starts<<<NN / T, T, 0, st>>>(batch[g], g);
    };
    auto set2set = [&](int g, cudaStream_t st) {
        k_escore<<<NN / 8, T, 0, st>>>(g, 0, batch[g]);
        k_attn<<<NB, T, 0, st>>>(g, 0);
        k_gates2<<<dim3(G4 / 128, NB / 64), T, 0, st>>>(Wih, g);
        k_lstm2<<<(NB * D6) / T, T, 0, st>>>(g);
        k_escore<<<NN / 8, T, 0, st>>>(g, 1, batch[g]);
        k_attn<<<NB, T, 0, st>>>(g, 1);
    };

    // fork: s1 joins the capture DAG via event
    cudaEventRecord(evA, s0);
    cudaStreamWaitEvent(s1, evA, 0);

    // s0: shared set2set precompute + graph0 pipeline ; s1: graph1 pipeline
    k_lstm1<<<(D6 + T - 1) / T, T, 0, s0>>>(bih, bhh);
    k_cvec<<<G4 / 8, T, 0, s0>>>(Wih, Whh, bih, bhh);
    gcn_chain(0, s0);
    gcn_chain(1, s1);

    // join for interaction (needs both graphs)
    cudaEventRecord(evB, s1);
    cudaStreamWaitEvent(s0, evB, 0);
    k_interact<<<NB, T, 0, s0>>>();

    // fork again for the two independent Set2Set chains
    cudaEventRecord(evC, s0);
    cudaStreamWaitEvent(s1, evC, 0);
    set2set(0, s0);
    set2set(1, s1);

    // join for MLP head
    cudaEventRecord(evD, s1);
    cudaStreamWaitEvent(s0, evD, 0);
    k_zero_z1pre<<<(NB * 256) / T, T, 0, s0>>>();
    k_mlp1_gemm<<<dim3(4, 4, 24), T, 0, s0>>>(Wp1);
    k_relu1<<<(NB * 256) / T, T, 0, s0>>>(bp1);
    k_mlp2<<<(NB * 128 * 32) / T, T, 0, s0>>>(Wp2, bp2);
    k_final<<<1, T, 0, s0>>>(Wp3, bp3, out);
}

// round 5
// speedup vs baseline: 1.9398x; 1.2259x over previous
#include <cuda_runtime.h>

#define NN   8192
#define NE   131072
#define NB   256
#define NHF  128
#define FIN  64
#define H3   384
#define D6   768
#define D12  1536
#define G4   3072
#define SMAXSEG 512   // max nodes per batch segment (mean 32, sd 5.6 — 512 is unreachable)

// ---------------- scratch ----------------
__device__ __align__(16) float g_h[2][NN * H3];
__device__ __align__(16) float g_x[2][NN * D6];
__device__ __align__(16) float g_xw[2][NN * NHF];
__device__ float g_deg[2][NN];
__device__ int   g_cnt[2][NN];
__device__ int   g_cursor[2][NN];
__device__ int   g_rowptr[2][NN + 1];
__device__ int   g_csrc[2][NE];
__device__ float g_cnrm[2][NE];
__device__ float g_dinv[2][NN];
__device__ int   g_starts[2][NB + 1];
__device__ float g_cvec[G4];
__device__ __align__(16) float g_rb[2][NB * D6];
__device__ __align__(16) float g_gates[2][NB * G4];
__device__ __align__(16) float g_z[NB * G4];
__device__ __align__(16) float g_z1pre[NB * 256];
__device__ __align__(16) float g_z2[NB * 128];

__device__ __forceinline__ float wredsum(float v) {
#pragma unroll
    for (int o = 16; o; o >>= 1) v += __shfl_xor_sync(0xffffffffu, v, o);
    return v;
}
__device__ __forceinline__ float sgm(float x) { return 1.f / (1.f + expf(-x)); }

// ---------------- CSR build (both graphs per launch) ----------------
__global__ void k_prep() {
    int i = blockIdx.x * blockDim.x + threadIdx.x;   // 0 .. 2*NN
    if (i < 2 * NN) {
        int g = i >> 13, n = i & (NN - 1);
        g_cnt[g][n] = 0;
        g_deg[g][n] = 0.f;
    }
}
__global__ void k_count(const int* __restrict__ ei1, const float* __restrict__ ew1,
                        const int* __restrict__ ei2, const float* __restrict__ ew2) {
    int g = blockIdx.y;
    const int* ei = g ? ei2 : ei1;
    const float* ew = g ? ew2 : ew1;
    int e = blockIdx.x * blockDim.x + threadIdx.x;
    if (e < NE) {
        int d = ei[NE + e];
        atomicAdd(&g_cnt[g][d], 1);
        atomicAdd(&g_deg[g][d], ew[e]);
    }
}
// grid (2) blocks of 1024: scan cnt -> rowptr/cursor ; dinv ; segment starts
__global__ void k_scan(const int* __restrict__ b1, const int* __restrict__ b2) {
    __shared__ int wsum[32];
    int g = blockIdx.x;
    int t = threadIdx.x, lane = t & 31, w = t >> 5;
    int base = t * 8;
    int loc[8], s = 0;
#pragma unroll
    for (int i = 0; i < 8; i++) { loc[i] = s; s += g_cnt[g][base + i]; }
    int x = s;
#pragma unroll
    for (int o = 1; o < 32; o <<= 1) {
        int y = __shfl_up_sync(0xffffffffu, x, o);
        if (lane >= o) x += y;
    }
    if (lane == 31) wsum[w] = x;
    __syncthreads();
    if (w == 0) {
        int y = wsum[lane];
#pragma unroll
        for (int o = 1; o < 32; o <<= 1) {
            int z = __shfl_up_sync(0xffffffffu, y, o);
            if (lane >= o) y += z;
        }
        wsum[lane] = y;
    }
    __syncthreads();
    int off = x - s + ((w > 0) ? wsum[w - 1] : 0);
#pragma unroll
    for (int i = 0; i < 8; i++) {
        g_rowptr[g][base + i] = off + loc[i];
        g_cursor[g][base + i] = off + loc[i];
    }
    if (t == 1023) g_rowptr[g][NN] = wsum[31];
    // dinv
#pragma unroll
    for (int i = 0; i < 8; i++) {
        int n = base + i;
        g_dinv[g][n] = rsqrtf(g_deg[g][n] + 1.0f);
    }
    // segment starts from sorted batch ids
    const int* batch = g ? b2 : b1;
#pragma unroll
    for (int i = 0; i < 8; i++) {
        int n = base + i;
        int b = batch[n];
        if (n == 0) {
            for (int bb = 0; bb <= b; bb++) g_starts[g][bb] = 0;
        } else {
            int pb = batch[n - 1];
            if (pb != b) for (int bb = pb + 1; bb <= b; bb++) g_starts[g][bb] = n;
        }
        if (n == NN - 1) for (int bb = b + 1; bb <= NB; bb++) g_starts[g][bb] = NN;
    }
}
__global__ void k_fill(const int* __restrict__ ei1, const float* __restrict__ ew1,
                       const int* __restrict__ ei2, const float* __restrict__ ew2) {
    int g = blockIdx.y;
    const int* ei = g ? ei2 : ei1;
    const float* ew = g ? ew2 : ew1;
    int e = blockIdx.x * blockDim.x + threadIdx.x;
    if (e >= NE) return;
    int s = ei[e], d = ei[NE + e];
    int pos = atomicAdd(&g_cursor[g][d], 1);
    g_csrc[g][pos] = s;
    g_cnrm[g][pos] = g_dinv[g][s] * ew[e] * g_dinv[g][d];
}

// ---------------- tiled GEMM: g_xw[g] = X[8192,K] @ W[K,128], both graphs ----------------
__global__ void k_gemm_xw(const float* __restrict__ f1, const float* __restrict__ f2,
                          int layer, const float* __restrict__ W) {
    __shared__ float As[16][64];
    __shared__ float Bs[16][68];
    int g = blockIdx.z;
    const float* X;
    int ldx, K;
    if (layer == 0) { X = g ? f2 : f1; ldx = FIN; K = FIN; }
    else            { X = g_h[g] + (layer - 1) * NHF; ldx = H3; K = NHF; }
    int tid = threadIdx.x, tx = tid & 15, ty = tid >> 4;
    int colBase = blockIdx.x * 64, rowBase = blockIdx.y * 64;
    float acc[4][4] = {};
    for (int k0 = 0; k0 < K; k0 += 16) {
#pragma unroll
        for (int l = 0; l < 4; l++) {
            int idx = tid + l * 256;
            int m = idx >> 4, kk = idx & 15;
            As[kk][m] = X[(size_t)(rowBase + m) * ldx + k0 + kk];
            Bs[kk][m] = W[(size_t)(k0 + kk) * NHF + colBase + m];
        }
        __syncthreads();
#pragma unroll
        for (int kk = 0; kk < 16; kk++) {
            float av[4], bv[4];
#pragma unroll
            for (int i = 0; i < 4; i++) av[i] = As[kk][ty * 4 + i];
#pragma unroll
            for (int j = 0; j < 4; j++) bv[j] = Bs[kk][tx * 4 + j];
#pragma unroll
            for (int i = 0; i < 4; i++)
#pragma unroll
                for (int j = 0; j < 4; j++) acc[i][j] += av[i] * bv[j];
        }
        __syncthreads();
    }
#pragma unroll
    for (int i = 0; i < 4; i++)
#pragma unroll
        for (int j = 0; j < 4; j++)
            g_xw[g][(size_t)(rowBase + ty * 4 + i) * NHF + colBase + tx * 4 + j] = acc[i][j];
}

// ---------------- fused GCN aggregation (both graphs) ----------------
__global__ void k_gather(int off, const float* __restrict__ bias) {
    int g = blockIdx.y;
    int n = blockIdx.x * 8 + (threadIdx.x >> 5);
    int lane = threadIdx.x & 31;
    if (n >= NN) return;
    const float4* xw4 = (const float4*)g_xw[g];
    float di = g_dinv[g][n];
    float sn = di * di;
    float4 bb = ((const float4*)bias)[lane];
    float4 sv = xw4[(size_t)n * 32 + lane];
    float ax = bb.x + sn * sv.x, ay = bb.y + sn * sv.y;
    float az = bb.z + sn * sv.z, aw = bb.w + sn * sv.w;
    int e0 = g_rowptr[g][n], e1 = g_rowptr[g][n + 1];
    for (int e = e0; e < e1; e++) {
        int s = g_csrc[g][e];
        float nm = g_cnrm[g][e];
        float4 v = xw4[(size_t)s * 32 + lane];
        ax += nm * v.x; ay += nm * v.y; az += nm * v.z; aw += nm * v.w;
    }
    ax = (ax >= 0.f) ? ax : 0.2f * ax;
    ay = (ay >= 0.f) ? ay : 0.2f * ay;
    az = (az >= 0.f) ? az : 0.2f * az;
    aw = (aw >= 0.f) ? aw : 0.2f * aw;
    float4* o = (float4*)(g_h[g] + (size_t)n * H3 + off);
    o[lane] = make_float4(ax, ay, az, aw);
}

// ---------------- L2 normalize (both graphs) ----------------
__global__ void k_l2() {
    int g = blockIdx.y;
    int warp = blockIdx.x * 8 + (threadIdx.x >> 5);
    int lane = threadIdx.x & 31;
    if (warp >= NN) return;
    const float* hr = g_h[g] + (size_t)warp * H3;
    float ss = 0.f;
#pragma unroll
    for (int t = 0; t < 12; t++) { float v = hr[lane + 32 * t]; ss += v * v; }
    ss = wredsum(ss);
    float inv = 1.f / fmaxf(sqrtf(ss), 1e-12f);
    float* xr = g_x[g] + (size_t)warp * D6;
#pragma unroll
    for (int t = 0; t < 12; t++) xr[lane + 32 * t] = hr[lane + 32 * t] * inv;
}

// ---------------- block-diagonal interaction (512 thr, one batch per block) ----------------
__global__ void __launch_bounds__(512) k_interact() {
    int b = blockIdx.x;
    int s1 = g_starts[0][b], e1 = g_starts[0][b + 1];
    int s2 = g_starts[1][b], e2 = g_starts[1][b + 1];
    int n1 = e1 - s1, n2 = e2 - s2, tot = n1 + n2;
    int lane = threadIdx.x & 31, w = threadIdx.x >> 5;
    for (int t = w; t < tot; t += 16) {
        const float *src, *oth;
        float* out;
        int row, obase, ocnt;
        if (t < n1) { row = s1 + t;        src = g_x[0]; oth = g_x[1]; obase = s2; ocnt = n2; out = g_x[0]; }
        else        { row = s2 + (t - n1); src = g_x[1]; oth = g_x[0]; obase = s1; ocnt = n1; out = g_x[1]; }
        const float* sr = src + (size_t)row * D6;
        float sv[12], acc[12];
#pragma unroll
        for (int q = 0; q < 12; q++) { sv[q] = sr[lane + 32 * q]; acc[q] = 0.f; }
        for (int jj = 0; jj < ocnt; jj++) {
            const float* vr = oth + (size_t)(obase + jj) * D6;
            float vv[12], p = 0.f;
#pragma unroll
            for (int q = 0; q < 12; q++) { vv[q] = vr[lane + 32 * q]; p += sv[q] * vv[q]; }
            p = wredsum(p);
#pragma unroll
            for (int q = 0; q < 12; q++) acc[q] += p * vv[q];
        }
        float* orow = out + (size_t)row * D6 + H3;
#pragma unroll
        for (int q = 0; q < 12; q++) orow[lane + 32 * q] = acc[q];
    }
}

// ---------------- cvec (side stream): hv recomputed per block; also zero z1pre ----------------
__global__ void k_cvec(const float* __restrict__ Wih, const float* __restrict__ Whh,
                       const float* __restrict__ bih, const float* __restrict__ bhh) {
    __shared__ float shv[D6];
    int tid = threadIdx.x, lane = tid & 31, w = tid >> 5;
    for (int j = tid; j < D6; j += 256) {
        float gi = bih[j] + bhh[j];
        float gg = bih[2 * D6 + j] + bhh[2 * D6 + j];
        float go = bih[3 * D6 + j] + bhh[3 * D6 + j];
        float c = sgm(gi) * tanhf(gg);
        shv[j] = sgm(go) * tanhf(c);
    }
    if (blockIdx.x < 256) g_z1pre[blockIdx.x * 256 + tid] = 0.f;
    __syncthreads();
    int gout = blockIdx.x * 8 + w;           // 384 blocks * 8 = 3072
    const float* wi = Wih + (size_t)gout * D12;
    const float* wh = Whh + (size_t)gout * D6;
    float p = 0.f;
#pragma unroll
    for (int t = 0; t < 24; t++) {
        int k = lane + 32 * t;
        p += shv[k] * (wi[k] + wh[k]);
    }
    p = wredsum(p);
    if (lane == 0) g_cvec[gout] = bih[gout] + bhh[gout] + p;
}

// ---------------- fused attention step 1: h from biases, scores, softmax, readout ----------------
__global__ void k_attn1(const float* __restrict__ bih, const float* __restrict__ bhh) {
    __shared__ float hq[D6];
    __shared__ float sc[SMAXSEG];
    __shared__ float red[256];
    int g = blockIdx.y, b = blockIdx.x;
    int tid = threadIdx.x, lane = tid & 31, w = tid >> 5;
    for (int j = tid; j < D6; j += 256) {
        float gi = bih[j] + bhh[j];
        float gg = bih[2 * D6 + j] + bhh[2 * D6 + j];
        float go = bih[3 * D6 + j] + bhh[3 * D6 + j];
        float c = sgm(gi) * tanhf(gg);
        hq[j] = sgm(go) * tanhf(c);
    }
    __syncthreads();
    int s = g_starts[g][b], e = g_starts[g][b + 1], cnt = e - s;
    float* rout = g_rb[g] + (size_t)b * D6;
    if (cnt <= 0) {
        for (int j = tid; j < D6; j += 256) rout[j] = 0.f;
        return;
    }
    const float* x = g_x[g];
    for (int t = w; t < cnt; t += 8) {
        const float* xr = x + (size_t)(s + t) * D6;
        float p = 0.f;
#pragma unroll
        for (int q = 0; q < 24; q++) p += xr[lane + 32 * q] * hq[lane + 32 * q];
        p = wredsum(p);
        if (lane == 0) sc[t] = p;
    }
    __syncthreads();
    float lm = -3.4e38f;
    for (int t = tid; t < cnt; t += 256) lm = fmaxf(lm, sc[t]);
    red[tid] = lm; __syncthreads();
    for (int o = 128; o > 0; o >>= 1) { if (tid < o) red[tid] = fmaxf(red[tid], red[tid + o]); __syncthreads(); }
    float m = red[0]; __syncthreads();
    float ls = 0.f;
    for (int t = tid; t < cnt; t += 256) { float ev = expf(sc[t] - m); sc[t] = ev; ls += ev; }
    red[tid] = ls; __syncthreads();
    for (int o = 128; o > 0; o >>= 1) { if (tid < o) red[tid] += red[tid + o]; __syncthreads(); }
    float inv = 1.f / red[0]; __syncthreads();
    float a0 = 0.f, a1 = 0.f, a2 = 0.f;
    for (int t = 0; t < cnt; t++) {
        float wv = sc[t];
        const float* xr = x + (size_t)(s + t) * D6;
        a0 += wv * xr[tid];
        a1 += wv * xr[tid + 256];
        a2 += wv * xr[tid + 512];
    }
    rout[tid] = a0 * inv;
    rout[tid + 256] = a1 * inv;
    rout[tid + 512] = a2 * inv;
}

// gates2[g] = g_rb[g] @ WihR^T + cvec   (64x64 tile, both graphs via blockIdx.z)
__global__ void k_gates2(const float* __restrict__ Wih) {
    __shared__ float As[16][64];
    __shared__ float Bs[16][68];
    int g = blockIdx.z;
    int tid = threadIdx.x, tx = tid & 15, ty = tid >> 4;
    int colBase = blockIdx.x * 64, rowBase = blockIdx.y * 64;
    const float* A = g_rb[g];
    const float* B = Wih + D6;
    float acc[4][4] = {};
    for (int k0 = 0; k0 < D6; k0 += 16) {
#pragma unroll
        for (int l = 0; l < 4; l++) {
            int idx = tid + l * 256;
            int m = idx >> 4, kk = idx & 15;
            As[kk][m] = A[(size_t)(rowBase + m) * D6 + k0 + kk];
            Bs[kk][m] = B[(size_t)(colBase + m) * D12 + k0 + kk];
        }
        __syncthreads();
#pragma unroll
        for (int kk = 0; kk < 16; kk++) {
            float av[4], bv[4];
#pragma unroll
            for (int i = 0; i < 4; i++) av[i] = As[kk][ty * 4 + i];
#pragma unroll
            for (int j = 0; j < 4; j++) bv[j] = Bs[kk][tx * 4 + j];
#pragma unroll
            for (int i = 0; i < 4; i++)
#pragma unroll
                for (int j = 0; j < 4; j++) acc[i][j] += av[i] * bv[j];
        }
        __syncthreads();
    }
#pragma unroll
    for (int i = 0; i < 4; i++) {
        int row = rowBase + ty * 4 + i;
#pragma unroll
        for (int j = 0; j < 4; j++) {
            int col = colBase + tx * 4 + j;
            g_gates[g][(size_t)row * G4 + col] = acc[i][j] + g_cvec[col];
        }
    }
}

// ---------------- fused attention step 2: lstm2 + scores + softmax + readout ----------------
__global__ void k_attn2(const float* __restrict__ bih, const float* __restrict__ bhh) {
    __shared__ float hq[D6];
    __shared__ float sc[SMAXSEG];
    __shared__ float red[256];
    int g = blockIdx.y, b = blockIdx.x;
    int tid = threadIdx.x, lane = tid & 31, w = tid >> 5;
    const float* gt = g_gates[g] + (size_t)b * G4;
    float* zb = g_z + (size_t)b * G4 + (g ? D12 : 0);
    for (int j = tid; j < D6; j += 256) {
        // step-1 cell state from biases
        float gi1 = bih[j] + bhh[j];
        float gg1 = bih[2 * D6 + j] + bhh[2 * D6 + j];
        float cv = sgm(gi1) * tanhf(gg1);
        // step-2 LSTM
        float gi = gt[j], gf = gt[D6 + j], gg = gt[2 * D6 + j], go = gt[3 * D6 + j];
        float c = sgm(gf) * cv + sgm(gi) * tanhf(gg);
        float h = sgm(go) * tanhf(c);
        hq[j] = h;
        zb[j] = h;                  // q_star h-slot
    }
    __syncthreads();
    int s = g_starts[g][b], e = g_starts[g][b + 1], cnt = e - s;
    float* rout = zb + D6;          // q_star r-slot
    if (cnt <= 0) {
        for (int j = tid; j < D6; j += 256) rout[j] = 0.f;
        return;
    }
    const float* x = g_x[g];
    for (int t = w; t < cnt; t += 8) {
        const float* xr = x + (size_t)(s + t) * D6;
        float p = 0.f;
#pragma unroll
        for (int q = 0; q < 24; q++) p += xr[lane + 32 * q] * hq[lane + 32 * q];
        p = wredsum(p);
        if (lane == 0) sc[t] = p;
    }
    __syncthreads();
    float lm = -3.4e38f;
    for (int t = tid; t < cnt; t += 256) lm = fmaxf(lm, sc[t]);
    red[tid] = lm; __syncthreads();
    for (int o = 128; o > 0; o >>= 1) { if (tid < o) red[tid] = fmaxf(red[tid], red[tid + o]); __syncthreads(); }
    float m = red[0]; __syncthreads();
    float ls = 0.f;
    for (int t = tid; t < cnt; t += 256) { float ev = expf(sc[t] - m); sc[t] = ev; ls += ev; }
    red[tid] = ls; __syncthreads();
    for (int o = 128; o > 0; o >>= 1) { if (tid < o) red[tid] += red[tid + o]; __syncthreads(); }
    float inv = 1.f / red[0]; __syncthreads();
    float a0 = 0.f, a1 = 0.f, a2 = 0.f;
    for (int t = 0; t < cnt; t++) {
        float wv = sc[t];
        const float* xr = x + (size_t)(s + t) * D6;
        a0 += wv * xr[tid];
        a1 += wv * xr[tid + 256];
        a2 += wv * xr[tid + 512];
    }
    rout[tid] = a0 * inv;
    rout[tid + 256] = a1 * inv;
    rout[tid + 512] = a2 * inv;
}

// ---------------- MLP head ----------------
__global__ void k_mlp1_gemm(const float* __restrict__ Wp1) {
    __shared__ float As[16][64];
    __shared__ float Bs[16][68];
    int tid = threadIdx.x, tx = tid & 15, ty = tid >> 4;
    int colBase = blockIdx.x * 64, rowBase = blockIdx.y * 64;
    int kBase = blockIdx.z * 128;
    float acc[4][4] = {};
    for (int k0 = 0; k0 < 128; k0 += 16) {
#pragma unroll
        for (int l = 0; l < 4; l++) {
            int idx = tid + l * 256;
            int m = idx >> 4, kk = idx & 15;
            As[kk][m] = g_z[(size_t)(rowBase + m) * G4 + kBase + k0 + kk];
            Bs[kk][m] = Wp1[(size_t)(colBase + m) * G4 + kBase + k0 + kk];
        }
        __syncthreads();
#pragma unroll
        for (int kk = 0; kk < 16; kk++) {
            float av[4], bv[4];
#pragma unroll
            for (int i = 0; i < 4; i++) av[i] = As[kk][ty * 4 + i];
#pragma unroll
            for (int j = 0; j < 4; j++) bv[j] = Bs[kk][tx * 4 + j];
#pragma unroll
            for (int i = 0; i < 4; i++)
#pragma unroll
                for (int j = 0; j < 4; j++) acc[i][j] += av[i] * bv[j];
        }
        __syncthreads();
    }
#pragma unroll
    for (int i = 0; i < 4; i++)
#pragma unroll
        for (int j = 0; j < 4; j++)
            atomicAdd(&g_z1pre[(size_t)(rowBase + ty * 4 + i) * 256 + colBase + tx * 4 + j],
                      acc[i][j]);
}
// relu fused on read
__global__ void k_mlp2(const float* __restrict__ bp1,
                       const float* __restrict__ Wp2, const float* __restrict__ bp2) {
    int gw = (blockIdx.x * blockDim.x + threadIdx.x) >> 5;
    int lane = threadIdx.x & 31;
    if (gw >= NB * 128) return;
    int b = gw >> 7, o = gw & 127;
    const float* zp = g_z1pre + (size_t)b * 256;
    const float* wr = Wp2 + (size_t)o * 256;
    float p = 0.f;
#pragma unroll
    for (int k = lane; k < 256; k += 32) {
        float zv = fmaxf(zp[k] + bp1[k], 0.f);
        p += zv * wr[k];
    }
    p = wredsum(p);
    if (lane == 0) g_z2[(size_t)b * 128 + o] = fmaxf(p + bp2[o], 0.f);
}
__global__ void k_final(const float* __restrict__ Wp3, const float* __restrict__ bp3,
                        float* __restrict__ out) {
    int b = blockIdx.x * blockDim.x + threadIdx.x;
    if (b >= NB) return;
    float p = bp3[0];
#pragma unroll 16
    for (int k = 0; k < 128; k++) p += g_z2[(size_t)b * 128 + k] * Wp3[k];
    out[b] = 1.f / (1.f + expf(-p));
}

// ---------------- launch sequence ----------------
extern "C" void kernel_launch(void* const* d_in, const int* in_sizes, int n_in,
                              void* d_out, int out_size) {
    const float* f1 = (const float*)d_in[0];
    const float* f2 = (const float*)d_in[1];
    const float* ea1 = (const float*)d_in[2];
    const float* ea2 = (const float*)d_in[3];
    const float* W[3]  = { (const float*)d_in[4], (const float*)d_in[6], (const float*)d_in[8] };
    const float* bW[3] = { (const float*)d_in[5], (const float*)d_in[7], (const float*)d_in[9] };
    const float* Wih = (const float*)d_in[10];
    const float* bih = (const float*)d_in[11];
    const float* Whh = (const float*)d_in[12];
    const float* bhh = (const float*)d_in[13];
    const float* Wp1 = (const float*)d_in[14];
    const float* bp1 = (const float*)d_in[15];
    const float* Wp2 = (const float*)d_in[16];
    const float* bp2 = (const float*)d_in[17];
    const float* Wp3 = (const float*)d_in[18];
    const float* bp3 = (const float*)d_in[19];
    const int* ei1 = (const int*)d_in[20];
    const int* ei2 = (const int*)d_in[21];
    const int* b1 = (const int*)d_in[22];
    const int* b2 = (const int*)d_in[23];
    float* out = (float*)d_out;

    static cudaStream_t s1 = (cudaStream_t)0;
    static cudaEvent_t evA, evB;
    static bool inited = false;
    if (!inited) {
        cudaStreamCreateWithFlags(&s1, cudaStreamNonBlocking);
        cudaEventCreateWithFlags(&evA, cudaEventDisableTiming);
        cudaEventCreateWithFlags(&evB, cudaEventDisableTiming);
        inited = true;
    }
    cudaStream_t s0 = (cudaStream_t)0;
    const int T = 256;

    // side branch: cvec + z1pre zero (needed before gates2 / mlp1)
    cudaEventRecord(evA, s0);
    cudaStreamWaitEvent(s1, evA, 0);
    k_cvec<<<G4 / 8, T, 0, s1>>>(Wih, Whh, bih, bhh);
    cudaEventRecord(evB, s1);

    // main: CSR + GCN (both graphs per launch)
    k_prep<<<2 * NN / T, T, 0, s0>>>();
    k_count<<<dim3(NE / T, 2), T, 0, s0>>>(ei1, ea1, ei2, ea2);
    k_scan<<<2, 1024, 0, s0>>>(b1, b2);
    k_fill<<<dim3(NE / T, 2), T, 0, s0>>>(ei1, ea1, ei2, ea2);
    for (int l = 0; l < 3; l++) {
        k_gemm_xw<<<dim3(2, NN / 64, 2), T, 0, s0>>>(f1, f2, l, W[l]);
        k_gather<<<dim3(NN / 8, 2), T, 0, s0>>>(l * NHF, bW[l]);
    }
    k_l2<<<dim3(NN / 8, 2), T, 0, s0>>>();
    k_interact<<<NB, 512, 0, s0>>>();

    // set2set (both graphs per launch)
    k_attn1<<<dim3(NB, 2), T, 0, s0>>>(bih, bhh);
    cudaStreamWaitEvent(s0, evB, 0);    // cvec + z1pre ready
    k_gates2<<<dim3(G4 / 64, NB / 64, 2), T, 0, s0>>>(Wih);
    k_attn2<<<dim3(NB, 2), T, 0, s0>>>(bih, bhh);

    // MLP head
    k_mlp1_gemm<<<dim3(4, 4, 24), T, 0, s0>>>(Wp1);
    k_mlp2<<<(NB * 128 * 32) / T, T, 0, s0>>>(bp1, Wp2, bp2);
    k_final<<<1, T, 0, s0>>>(Wp3, bp3, out);
}